// round 1
// baseline (speedup 1.0000x reference)
#include <cuda_runtime.h>

#define BB 16
#define LL 128
#define PPTOT 8192
#define PCHUNK 256
#define NTHREADS 128

// Per-batch accumulators: [soft, log, hsa, pauli] x 16 batches
__device__ float g_acc[BB * 4];

__device__ __forceinline__ float rsqrt_a(float x) { float y; asm("rsqrt.approx.f32 %0,%1;" : "=f"(y) : "f"(x)); return y; }
__device__ __forceinline__ float sqrt_a(float x)  { float y; asm("sqrt.approx.f32 %0,%1;"  : "=f"(y) : "f"(x)); return y; }
__device__ __forceinline__ float rcp_a(float x)   { float y; asm("rcp.approx.f32 %0,%1;"   : "=f"(y) : "f"(x)); return y; }
__device__ __forceinline__ float ex2_a(float x)   { float y; asm("ex2.approx.f32 %0,%1;"   : "=f"(y) : "f"(x)); return y; }

__global__ void zero_kernel() {
    if (threadIdx.x < BB * 4) g_acc[threadIdx.x] = 0.0f;
}

__global__ void __launch_bounds__(NTHREADS) pair_kernel(
    const float* __restrict__ posL, const float* __restrict__ posP,
    const float* __restrict__ qL,   const float* __restrict__ qP,
    const float* __restrict__ xL,   const float* __restrict__ xP,
    const float* __restrict__ vdw,  const float* __restrict__ epst)
{
    __shared__ float4 sA[LL];  // (pos.x, pos.y, pos.z, 83.015*qL)
    __shared__ float4 sB[LL];  // (radii_L, sqrt(eps_L), x_L[0], 0)

    const int b   = blockIdx.y;
    const int tid = threadIdx.x;

    // --- stage ligand data in shared ---
    if (tid < LL) {
        const int l = tid;
        const float* xl = xL + ((size_t)b * LL + l) * 9;
        float rl = 0.0f, el = 0.0f;
#pragma unroll
        for (int i = 0; i < 9; i++) {
            float v = xl[i];
            rl = fmaf(v, vdw[i],  rl);
            el = fmaf(v, epst[i], el);
        }
        el = fmaxf(el, 0.0f);
        const float* pl = posL + ((size_t)b * LL + l) * 3;
        sA[l] = make_float4(pl[0], pl[1], pl[2], 83.015f * qL[b * LL + l]);
        sB[l] = make_float4(rl, sqrt_a(el), xl[0], 0.0f);
    }
    __syncthreads();

    // --- per-thread protein atoms: 2 p's per thread ---
    int pidx[2];
    pidx[0] = blockIdx.x * PCHUNK + tid;
    pidx[1] = pidx[0] + NTHREADS;

    float px[2], py[2], pz[2], qp[2], rP[2], seP4[2], x0p[2];
#pragma unroll
    for (int j = 0; j < 2; j++) {
        const size_t base = (size_t)b * PPTOT + pidx[j];
        const float* pp = posP + base * 3;
        px[j] = pp[0]; py[j] = pp[1]; pz[j] = pp[2];
        qp[j] = qP[base];
        const float* xp = xP + base * 4;
        float x0 = xp[0], x1 = xp[1], x2 = xp[2], x3 = xp[3];
        rP[j]   = fmaf(x0, 1.7f, fmaf(x1, 1.55f, fmaf(x2, 1.52f, x3 * 1.8f)));
        float eP = fmaf(x0, 0.1f, fmaf(x1, 0.1f, fmaf(x2, 0.15f, x3 * 0.2f)));
        seP4[j] = 4.0f * sqrt_a(eP);
        x0p[j]  = x0;
    }

    float acc_s[2] = {0.f, 0.f};
    float acc_l[2] = {0.f, 0.f};
    float acc_h[2] = {0.f, 0.f};
    float acc_p[2] = {0.f, 0.f};

#pragma unroll 4
    for (int l = 0; l < LL; l++) {
        const float4 a = sA[l];
        const float4 c = sB[l];
#pragma unroll
        for (int j = 0; j < 2; j++) {
            float dx = a.x - px[j];
            float dy = a.y - py[j];
            float dz = a.z - pz[j];
            float d2 = fmaf(dx, dx, fmaf(dy, dy, dz * dz));

            float sig  = c.x + rP[j];
            float sig2 = sig * sig;
            float s2   = fmaf(sig2, 2.0f, d2 + 1e-8f);   // dist_sq + ALPHA*sigma^2 + 1e-8
            float isd  = rsqrt_a(s2);                     // 1/soft_dist

            // e_elec = 200*tanh(eer/200); |z| small -> odd degree-7 polynomial
            float eer = a.w * qp[j] * isd;
            float z   = eer * 0.005f;
            float w   = z * z;
            float pl7 = fmaf(w, fmaf(w, fmaf(w, -5.396825397e-2f, 1.333333333e-1f), -3.333333333e-1f), 1.0f);
            float ee  = eer * pl7;

            // LJ soft-core: ratio <= 1/sqrt(2) -> e_vdw_raw <= 0 always
            float ratio = sig * isd;
            float r2    = ratio * ratio;
            float r6    = r2 * r2 * r2;
            float evr   = (c.y * seP4[j]) * fmaf(r6, r6, -r6);   // 4*eps_ij*(r12 - r6) <= 0
            // e_vdw_grad = -10*tanh(-evr/10) ~= evr - evr^3/300 (|evr|<=~0.13)
            float ev    = fmaf((evr * evr) * evr, -3.3333333333e-3f, evr);

            float d    = sqrt_a(d2 + 1e-8f);
            // dist_mask = sigmoid((12-d)*2) = 1/(1 + 2^((d-12)*2*log2(e)))
            float ex   = ex2_a(fmaf(d, 2.8853900817779268f, -34.624680981335124f));
            float mask = rcp_a(1.0f + ex);

            // hsa term: 1/(1+(d/4)^4) = 256/(256 + d^4) ; 256 factored out to epilogue
            float hr = rcp_a(fmaf(d2, d2, 256.0f));
            acc_h[j] = fmaf((c.z * x0p[j]) * hr, mask, acc_h[j]);

            // pauli overlap
            float ov = fmaxf(fmaf(sig, 0.6f, -d), 0.0f);
            acc_p[j] = fmaf(ov, ov, acc_p[j]);

            // log branch clamp
            float lv = fminf(fmaxf(evr, -10.0f), 500.0f);

            acc_s[j] = fmaf(ee + ev, mask, acc_s[j]);
            acc_l[j] = fmaf(ee + lv, mask, acc_l[j]);
        }
    }

    // --- reduce ---
    float v0 = acc_s[0] + acc_s[1];
    float v1 = acc_l[0] + acc_l[1];
    float v2 = acc_h[0] + acc_h[1];
    float v3 = acc_p[0] + acc_p[1];
#pragma unroll
    for (int off = 16; off > 0; off >>= 1) {
        v0 += __shfl_xor_sync(0xFFFFFFFFu, v0, off);
        v1 += __shfl_xor_sync(0xFFFFFFFFu, v1, off);
        v2 += __shfl_xor_sync(0xFFFFFFFFu, v2, off);
        v3 += __shfl_xor_sync(0xFFFFFFFFu, v3, off);
    }
    if ((tid & 31) == 0) {
        atomicAdd(&g_acc[b * 4 + 0], v0);
        atomicAdd(&g_acc[b * 4 + 1], v1);
        atomicAdd(&g_acc[b * 4 + 2], v2);
        atomicAdd(&g_acc[b * 4 + 3], v3);
    }
}

__global__ void finish_kernel(float* __restrict__ out) {
    const int b = threadIdx.x;
    if (b < BB) {
        float s  = g_acc[b * 4 + 0];
        float lg = g_acc[b * 4 + 1];
        float h  = g_acc[b * 4 + 2];
        float pa = g_acc[b * 4 + 3];

        float e_hsa   = -0.5f * 256.0f * h;
        float e_pauli = 0.95257412682243336f * 100.0f * pa;  // sigmoid(3.0)*100

        float e_raw  = s + 5.0f * e_hsa + e_pauli;
        float e_hard = fminf(e_pauli, 10000.0f);
        float e_soft_log = fminf(fmaxf(lg + 5.0f * e_hsa, -500.0f), 5000.0f);
        float loge = fminf(e_soft_log + e_hard, 1000000.0f);

        out[b]      = e_raw;        // e_raw[16]
        out[16 + b] = e_hard;       // e_hard_log[16]
        out[33 + b] = loge;         // log_energy_val[16]
    }
    if (b == 0) out[32] = 2.0f;     // ALPHA scalar
}

extern "C" void kernel_launch(void* const* d_in, const int* in_sizes, int n_in,
                              void* d_out, int out_size) {
    const float* posL = (const float*)d_in[0];
    const float* posP = (const float*)d_in[1];
    const float* qL   = (const float*)d_in[2];
    const float* qP   = (const float*)d_in[3];
    const float* xL   = (const float*)d_in[4];
    const float* xP   = (const float*)d_in[5];
    const float* vdw  = (const float*)d_in[6];
    const float* epst = (const float*)d_in[7];
    float* out = (float*)d_out;

    zero_kernel<<<1, 64>>>();
    dim3 grid(PPTOT / PCHUNK, BB);
    pair_kernel<<<grid, NTHREADS>>>(posL, posP, qL, qP, xL, xP, vdw, epst);
    finish_kernel<<<1, 32>>>(out);
}

// round 2
// speedup vs baseline: 1.1535x; 1.1535x over previous
#include <cuda_runtime.h>

#define BB 16
#define LTOT 128
#define LHALF 64
#define PPTOT 8192
#define NTHREADS 128
#define XCHUNKS 32                 // PPTOT / (NTHREADS*2)
#define ZSPLIT 2
#define NTILES (XCHUNKS * ZSPLIT)  // 64 partial slots per batch
#define TOTBLK (XCHUNKS * BB * ZSPLIT)  // 1024

__device__ float g_part[BB][4][NTILES];
__device__ unsigned int g_cnt = 0;

typedef unsigned long long f2;

__device__ __forceinline__ float rsqrt_a(float x) { float y; asm("rsqrt.approx.f32 %0,%1;" : "=f"(y) : "f"(x)); return y; }
__device__ __forceinline__ float sqrt_a(float x)  { float y; asm("sqrt.approx.f32 %0,%1;"  : "=f"(y) : "f"(x)); return y; }
__device__ __forceinline__ float rcp_a(float x)   { float y; asm("rcp.approx.f32 %0,%1;"   : "=f"(y) : "f"(x)); return y; }
__device__ __forceinline__ float ex2_a(float x)   { float y; asm("ex2.approx.f32 %0,%1;"   : "=f"(y) : "f"(x)); return y; }

__device__ __forceinline__ f2 pk(float lo, float hi) { f2 r; asm("mov.b64 %0,{%1,%2};" : "=l"(r) : "f"(lo), "f"(hi)); return r; }
__device__ __forceinline__ void upk(f2 v, float& lo, float& hi) { asm("mov.b64 {%0,%1},%2;" : "=f"(lo), "=f"(hi) : "l"(v)); }
__device__ __forceinline__ f2 fma2(f2 a, f2 b, f2 c) { f2 r; asm("fma.rn.f32x2 %0,%1,%2,%3;" : "=l"(r) : "l"(a), "l"(b), "l"(c)); return r; }
__device__ __forceinline__ f2 mul2(f2 a, f2 b) { f2 r; asm("mul.rn.f32x2 %0,%1,%2;" : "=l"(r) : "l"(a), "l"(b)); return r; }
__device__ __forceinline__ f2 add2(f2 a, f2 b) { f2 r; asm("add.rn.f32x2 %0,%1,%2;" : "=l"(r) : "l"(a), "l"(b)); return r; }

__global__ void __launch_bounds__(NTHREADS) pair_kernel(
    const float* __restrict__ posL, const float* __restrict__ posP,
    const float* __restrict__ qL,   const float* __restrict__ qP,
    const float* __restrict__ xL,   const float* __restrict__ xP,
    const float* __restrict__ vdw,  const float* __restrict__ epst,
    float* __restrict__ out)
{
    // Ligand scalars, pre-duplicated so LDS.64 loads straight into packed regs.
    // [l][k]: 0=x 1=y 2=z 3=83.015*q 4=radii 5=sqrt(eps) 6=x_L[0], 7=pad
    __shared__ float2 sL[LHALF][8];
    __shared__ float  red[4][4];
    __shared__ int    s_last;

    const int b   = blockIdx.y;
    const int tid = threadIdx.x;
    const int lbase = blockIdx.z * LHALF;

    if (tid < LHALF) {
        const int l = lbase + tid;
        const float* xl = xL + ((size_t)b * LTOT + l) * 9;
        float rl = 0.0f, el = 0.0f;
#pragma unroll
        for (int i = 0; i < 9; i++) {
            float v = xl[i];
            rl = fmaf(v, vdw[i],  rl);
            el = fmaf(v, epst[i], el);
        }
        el = fmaxf(el, 0.0f);
        const float* pl = posL + ((size_t)b * LTOT + l) * 3;
        float aw = 83.015f * qL[b * LTOT + l];
        float se = sqrt_a(el);
        sL[tid][0] = make_float2(pl[0], pl[0]);
        sL[tid][1] = make_float2(pl[1], pl[1]);
        sL[tid][2] = make_float2(pl[2], pl[2]);
        sL[tid][3] = make_float2(aw, aw);
        sL[tid][4] = make_float2(rl, rl);
        sL[tid][5] = make_float2(se, se);
        sL[tid][6] = make_float2(xl[0], xl[0]);
    }
    __syncthreads();

    // --- per-thread protein atoms (2, packed) ---
    const int p0 = blockIdx.x * (NTHREADS * 2) + tid;
    const int p1 = p0 + NTHREADS;
    f2 npx, npy, npz, qp, rp, sep4, x0p;
    {
        const size_t b0 = (size_t)b * PPTOT + p0;
        const size_t b1 = (size_t)b * PPTOT + p1;
        const float* pp0 = posP + b0 * 3;
        const float* pp1 = posP + b1 * 3;
        npx = pk(-pp0[0], -pp1[0]);
        npy = pk(-pp0[1], -pp1[1]);
        npz = pk(-pp0[2], -pp1[2]);
        qp  = pk(qP[b0], qP[b1]);
        const float* xp0 = xP + b0 * 4;
        const float* xp1 = xP + b1 * 4;
        float r0 = fmaf(xp0[0], 1.7f, fmaf(xp0[1], 1.55f, fmaf(xp0[2], 1.52f, xp0[3] * 1.8f)));
        float r1 = fmaf(xp1[0], 1.7f, fmaf(xp1[1], 1.55f, fmaf(xp1[2], 1.52f, xp1[3] * 1.8f)));
        float e0 = fmaf(xp0[0], 0.1f, fmaf(xp0[1], 0.1f, fmaf(xp0[2], 0.15f, xp0[3] * 0.2f)));
        float e1 = fmaf(xp1[0], 0.1f, fmaf(xp1[1], 0.1f, fmaf(xp1[2], 0.15f, xp1[3] * 0.2f)));
        rp   = pk(r0, r1);
        sep4 = pk(4.0f * sqrt_a(e0), 4.0f * sqrt_a(e1));
        x0p  = pk(xp0[0], xp1[0]);
    }

    // packed constants
    const f2 C_EPS  = pk(1e-8f, 1e-8f);
    const f2 C_Z    = pk(0.005f, 0.005f);
    const f2 C_T1   = pk(-0.333333333f, -0.333333333f);
    const f2 C_T2   = pk(0.133333333f, 0.133333333f);
    const f2 C_ONE  = pk(1.0f, 1.0f);
    const f2 C_NEG1 = pk(-1.0f, -1.0f);
    const f2 C_M300 = pk(-3.3333333333e-3f, -3.3333333333e-3f);
    const f2 C_K1   = pk(2.8853900817779268f, 2.8853900817779268f);
    const f2 C_K0   = pk(-34.624680981335124f, -34.624680981335124f);
    const f2 C_256  = pk(256.0f, 256.0f);

    f2 acc_s = 0ull, acc_l = 0ull, acc_h = 0ull;
    float accp0 = 0.0f, accp1 = 0.0f;

#pragma unroll 4
    for (int l = 0; l < LHALF; l++) {
        const f2* sl = (const f2*)sL[l];
        f2 dx = add2(sl[0], npx);
        f2 dy = add2(sl[1], npy);
        f2 dz = add2(sl[2], npz);
        f2 d2 = fma2(dx, dx, fma2(dy, dy, fma2(dz, dz, C_EPS)));  // dist_sq + 1e-8
        f2 sig  = add2(sl[4], rp);
        f2 sig2x = add2(sig, sig);
        f2 s2   = fma2(sig, sig2x, d2);                           // + 2*sigma^2
        float s2l, s2h; upk(s2, s2l, s2h);
        f2 isd = pk(rsqrt_a(s2l), rsqrt_a(s2h));                  // 1/soft_dist

        // e_elec = 200*tanh(eer/200), |z|<=0.2 -> odd degree-5 poly
        f2 eer = mul2(mul2(sl[3], qp), isd);
        f2 z   = mul2(eer, C_Z);
        f2 w   = mul2(z, z);
        f2 p   = fma2(w, fma2(w, C_T2, C_T1), C_ONE);
        f2 ee  = mul2(eer, p);

        // LJ soft-core (always <= 0): evr = ce * r6 * (r6 - 1)
        f2 ratio = mul2(sig, isd);
        f2 r2 = mul2(ratio, ratio);
        f2 r4 = mul2(r2, r2);
        f2 r6 = mul2(r4, r2);
        f2 ce = mul2(sl[5], sep4);
        f2 r6m1 = add2(r6, C_NEG1);
        f2 evr  = mul2(mul2(ce, r6), r6m1);
        f2 e2 = mul2(evr, evr);
        f2 e3 = mul2(e2, evr);
        f2 suml = add2(ee, evr);                  // log branch: clamp is identity
        f2 sums = fma2(e3, C_M300, suml);         // tanh cubic correction

        float d2l, d2h; upk(d2, d2l, d2h);
        float dl = sqrt_a(d2l), dh = sqrt_a(d2h);
        f2 d = pk(dl, dh);

        // mask = 1/(1+ex); fused with hsa: rab = 1/((1+ex)*(d^4+256))
        f2 exarg = fma2(d, C_K1, C_K0);
        float xal, xah; upk(exarg, xal, xah);
        f2 ex = pk(ex2_a(xal), ex2_a(xah));
        f2 hd = fma2(d2, d2, C_256);              // (d2+1e-8)^2 + 256 (exact per ref)
        f2 ab = fma2(ex, hd, hd);                 // (1+ex)*hd
        float abl, abh; upk(ab, abl, abh);
        f2 rab  = pk(rcp_a(abl), rcp_a(abh));
        f2 mask = mul2(hd, rab);

        f2 wcc = mul2(sl[6], x0p);
        acc_h = fma2(wcc, rab, acc_h);            // hsa_term*mask = 256*rab (256 in epilogue)
        acc_s = fma2(sums, mask, acc_s);
        acc_l = fma2(suml, mask, acc_l);

        // pauli overlap (scalar; fmaxf -> alu pipe)
        float sgl, sgh; upk(sig, sgl, sgh);
        float ovl = fmaxf(fmaf(sgl, 0.6f, -dl), 0.0f);
        float ovh = fmaxf(fmaf(sgh, 0.6f, -dh), 0.0f);
        accp0 = fmaf(ovl, ovl, accp0);
        accp1 = fmaf(ovh, ovh, accp1);
    }

    // --- block reduction ---
    float v0l, v0h, v1l, v1h, v2l, v2h;
    upk(acc_s, v0l, v0h);
    upk(acc_l, v1l, v1h);
    upk(acc_h, v2l, v2h);
    float v0 = v0l + v0h, v1 = v1l + v1h, v2 = v2l + v2h, v3 = accp0 + accp1;
#pragma unroll
    for (int off = 16; off > 0; off >>= 1) {
        v0 += __shfl_xor_sync(0xFFFFFFFFu, v0, off);
        v1 += __shfl_xor_sync(0xFFFFFFFFu, v1, off);
        v2 += __shfl_xor_sync(0xFFFFFFFFu, v2, off);
        v3 += __shfl_xor_sync(0xFFFFFFFFu, v3, off);
    }
    const int wid = tid >> 5;
    if ((tid & 31) == 0) {
        red[wid][0] = v0; red[wid][1] = v1; red[wid][2] = v2; red[wid][3] = v3;
    }
    __syncthreads();
    const int slot = blockIdx.z * XCHUNKS + blockIdx.x;
    if (tid < 4) {
        float s = red[0][tid] + red[1][tid] + red[2][tid] + red[3][tid];
        g_part[b][tid][slot] = s;
    }
    __threadfence();
    if (tid == 0) {
        unsigned int old = atomicAdd(&g_cnt, 1u);
        s_last = (old == TOTBLK - 1) ? 1 : 0;
    }
    __syncthreads();
    if (!s_last) return;

    // --- last block: final reduction + epilogue ---
    __threadfence();
    __shared__ float fin[BB][4];
    if (tid < BB * 4) {
        const int fb = tid >> 2, fc = tid & 3;
        float s = 0.0f;
#pragma unroll 8
        for (int i = 0; i < NTILES; i++) s += g_part[fb][fc][i];
        fin[fb][fc] = s;
    }
    __syncthreads();
    if (tid < BB) {
        float s  = fin[tid][0];
        float lg = fin[tid][1];
        float h  = fin[tid][2];
        float pa = fin[tid][3];

        float e_hsa   = -0.5f * 256.0f * h;
        float e_pauli = 95.257412682243336f * pa;   // sigmoid(3.0)*100

        float e_raw  = s + 5.0f * e_hsa + e_pauli;
        float e_hard = fminf(e_pauli, 10000.0f);
        float e_soft_log = fminf(fmaxf(lg + 5.0f * e_hsa, -500.0f), 5000.0f);
        float loge = fminf(e_soft_log + e_hard, 1000000.0f);

        out[tid]      = e_raw;
        out[16 + tid] = e_hard;
        out[33 + tid] = loge;
    }
    if (tid == 0) {
        out[32] = 2.0f;   // ALPHA
        g_cnt = 0;        // reset for next graph replay (deterministic)
    }
}

extern "C" void kernel_launch(void* const* d_in, const int* in_sizes, int n_in,
                              void* d_out, int out_size) {
    const float* posL = (const float*)d_in[0];
    const float* posP = (const float*)d_in[1];
    const float* qL   = (const float*)d_in[2];
    const float* qP   = (const float*)d_in[3];
    const float* xL   = (const float*)d_in[4];
    const float* xP   = (const float*)d_in[5];
    const float* vdw  = (const float*)d_in[6];
    const float* epst = (const float*)d_in[7];
    float* out = (float*)d_out;

    dim3 grid(XCHUNKS, BB, ZSPLIT);
    pair_kernel<<<grid, NTHREADS>>>(posL, posP, qL, qP, xL, xP, vdw, epst, out);
}